// round 3
// baseline (speedup 1.0000x reference)
#include <cuda_runtime.h>

#define NB 4096
#define L 64
#define D 128
#define TMAX 65            // counts are in [0, 64]
#define GRID 512           // 8 batches per block, single balanced wave
#define THREADS 256
#define BPB 8              // batches per block

// Lookup table: T[a][e] = sum_d relu(a*W1[d]+b1[d]) * W2[d][e] + b2[e]
__device__ float g_T[TMAX * D];

__global__ __launch_bounds__(D) void build_table_kernel(
    const float* __restrict__ W1, const float* __restrict__ b1,
    const float* __restrict__ W2, const float* __restrict__ b2)
{
    __shared__ float h[D];
    const int a = blockIdx.x;      // 0..64
    const int e = threadIdx.x;     // 0..127
    h[e] = fmaxf((float)a * W1[e] + b1[e], 0.0f);
    __syncthreads();
    float acc = b2[e];
    #pragma unroll 8
    for (int d = 0; d < D; ++d)
        acc = fmaf(h[d], W2[d * D + e], acc);
    g_T[a * D + e] = acc;
}

__global__ __launch_bounds__(THREADS) void nif_encoder_kernel(
    const int* __restrict__ src_ids, const int* __restrict__ dst_ids,
    const int* __restrict__ src_nb,  const int* __restrict__ dst_nb,
    float* __restrict__ out)
{
    __shared__ float sT[TMAX * D];          // 33280 B, staged once
    __shared__ int   s_srcL[2][L], s_dstL[2][L];   // lists for 2 in-flight batches
    __shared__ int   s_cd[BPB], s_cs[BPB];         // per-batch-slot counters (no reuse races)
    __shared__ int   s_a[BPB * 2 * L];             // packed a0 | (a1<<8) per row

    const int tid  = threadIdx.x;
    const int lane = tid & 31;
    const int wrp  = tid >> 5;              // 0..7
    const int base = blockIdx.x * BPB;
    const size_t half = (size_t)NB * L * D;

    // Stage the lookup table once
    #pragma unroll
    for (int i = tid; i < TMAX * D; i += THREADS) sT[i] = g_T[i];
    if (tid < BPB) { s_cd[tid] = 0; s_cs[tid] = 0; }

    // ================= Phase 1: compute all 8 batches' (a0,a1) =================
    // Process 2 batches per iteration: threads 0-127 -> batch A, 128-255 -> batch B.
    #pragma unroll
    for (int it = 0; it < BPB / 2; ++it) {
        const int p    = tid >> 7;                // 0 or 1 (which batch of the pair)
        const int h    = tid & 127;               // thread-in-batch
        const int slot = it * 2 + p;              // 0..7
        const int b    = base + slot;

        // load this batch's lists (64 src + 64 dst ints, 128 threads)
        if (h < L) s_srcL[p][h]     = __ldg(&src_nb[b * L + h]);
        else       s_dstL[p][h - L] = __ldg(&dst_nb[b * L + (h - L)]);
        __syncthreads();

        const int sid = __ldg(&src_ids[b]);
        const int did = __ldg(&dst_ids[b]);

        int c_self = 0, c_other = 0, my_x;
        if (h < L) {
            if (s_dstL[p][h] == sid) atomicAdd(&s_cd[slot], 1);
            my_x = s_srcL[p][h];
            #pragma unroll
            for (int j = 0; j < L; ++j) {
                c_self  += (my_x == s_srcL[p][j]);
                c_other += (my_x == s_dstL[p][j]);
            }
        } else {
            const int i = h - L;
            if (s_srcL[p][i] == did) atomicAdd(&s_cs[slot], 1);
            my_x = s_dstL[p][i];
            #pragma unroll
            for (int j = 0; j < L; ++j) {
                c_self  += (my_x == s_dstL[p][j]);
                c_other += (my_x == s_srcL[p][j]);
            }
        }
        __syncthreads();

        // dict-mutation overrides (exact reference semantics), pack into s_a
        {
            const int  cd     = s_cd[slot];
            const int  cs     = s_cs[slot];
            const bool same   = (sid == did);
            const bool in_dst = (cd > 0);                      // srcid_in_dst
            const bool cond2  = (cs > 0) || (same && in_dst);
            const int  v2     = (same && in_dst) ? cd : cs;
            int a0, a1;
            if (h < L) {
                a0 = c_self;                                         // c_src
                a1 = (my_x == did && cond2)  ? v2 : c_other;         // src_col1
            } else {
                a0 = (my_x == sid && in_dst) ? cd : c_other;         // dst_col0
                a1 = c_self;                                         // c_dst
            }
            s_a[slot * 2 * L + h] = a0 | (a1 << 8);
        }
        // next iter's list loads are safe: all list READS completed before the
        // sync above; this section touches only registers / s_cd / s_a.
    }
    __syncthreads();

    // ================= Phase 2: uninterrupted streaming store ==================
    // 128 independent float4 stores per thread, no barriers.
    for (int bb = 0; bb < BPB; ++bb) {
        const int b = base + bb;
        float* out_src = out + (size_t)b * L * D;
        float* out_dst = out + half + (size_t)b * L * D;
        const int* sa  = &s_a[bb * 2 * L];

        #pragma unroll
        for (int it = 0; it < 16; ++it) {
            const int r      = it * 8 + wrp;
            const int packed = sa[r];
            const int a0     = packed & 0xFF;
            const int a1     = packed >> 8;
            const float4 t0 = *(const float4*)&sT[a0 * D + lane * 4];
            const float4 t1 = *(const float4*)&sT[a1 * D + lane * 4];
            float4 o;
            o.x = t0.x + t1.x; o.y = t0.y + t1.y;
            o.z = t0.z + t1.z; o.w = t0.w + t1.w;
            float* dst_row = (r < L) ? (out_src + r * D) : (out_dst + (r - L) * D);
            __stcs((float4*)&dst_row[lane * 4], o);
        }
    }
}

extern "C" void kernel_launch(void* const* d_in, const int* in_sizes, int n_in,
                              void* d_out, int out_size)
{
    const int*   src_ids = (const int*)  d_in[0];
    const int*   dst_ids = (const int*)  d_in[1];
    const int*   src_nb  = (const int*)  d_in[2];
    const int*   dst_nb  = (const int*)  d_in[3];
    const float* W1      = (const float*)d_in[4];
    const float* b1      = (const float*)d_in[5];
    const float* W2      = (const float*)d_in[6];
    const float* b2      = (const float*)d_in[7];
    float*       out     = (float*)d_out;

    build_table_kernel<<<TMAX, D>>>(W1, b1, W2, b2);
    nif_encoder_kernel<<<GRID, THREADS>>>(src_ids, dst_ids, src_nb, dst_nb, out);
}

// round 4
// speedup vs baseline: 1.2636x; 1.2636x over previous
#include <cuda_runtime.h>

#define NB 4096
#define L 64
#define D 128
#define TMAX 65            // counts are in [0, 64]
#define BPB 2              // batches per block (one per half-block)
#define GRID (NB / BPB)    // 2048 blocks
#define THREADS 256

// Lookup table: T[a][e] = sum_d relu(a*W1[d]+b1[d]) * W2[d][e] + b2[e]
__device__ float g_T[TMAX * D];

__global__ __launch_bounds__(D) void build_table_kernel(
    const float* __restrict__ W1, const float* __restrict__ b1,
    const float* __restrict__ W2, const float* __restrict__ b2)
{
    __shared__ float h[D];
    const int a = blockIdx.x;      // 0..64
    const int e = threadIdx.x;     // 0..127
    h[e] = fmaxf((float)a * W1[e] + b1[e], 0.0f);
    __syncthreads();
    float acc = b2[e];
    #pragma unroll 8
    for (int d = 0; d < D; ++d)
        acc = fmaf(h[d], W2[d * D + e], acc);
    g_T[a * D + e] = acc;
}

__global__ __launch_bounds__(THREADS) void nif_encoder_kernel(
    const int* __restrict__ src_ids, const int* __restrict__ dst_ids,
    const int* __restrict__ src_nb,  const int* __restrict__ dst_nb,
    float* __restrict__ out)
{
    // ~2.6 KB smem total -> occupancy is regs-limited, not smem-limited
    __shared__ int s_srcL[BPB][L], s_dstL[BPB][L];
    __shared__ int s_cd[BPB], s_cs[BPB];
    __shared__ int s_a[BPB][2 * L];          // packed a0 | (a1<<8)

    const int tid  = threadIdx.x;
    const int lane = tid & 31;
    const int wrp  = tid >> 5;               // 0..7
    const int p    = tid >> 7;               // which batch of this block (0/1)
    const int h    = tid & 127;              // thread-in-batch
    const int base = blockIdx.x * BPB;
    const size_t half = (size_t)NB * L * D;

    if (tid < BPB) { s_cd[tid] = 0; s_cs[tid] = 0; }

    // ---- load both batches' neighbor lists (each half-block loads its own) ----
    const int b = base + p;
    if (h < L) s_srcL[p][h]     = __ldg(&src_nb[b * L + h]);
    else       s_dstL[p][h - L] = __ldg(&dst_nb[b * L + (h - L)]);
    __syncthreads();

    const int sid = __ldg(&src_ids[b]);
    const int did = __ldg(&dst_ids[b]);

    // ---- counts: each half-block does its own batch ----
    int c_self = 0, c_other = 0, my_x;
    if (h < L) {
        if (s_dstL[p][h] == sid) atomicAdd(&s_cd[p], 1);
        my_x = s_srcL[p][h];
        #pragma unroll
        for (int j = 0; j < L; ++j) {
            c_self  += (my_x == s_srcL[p][j]);
            c_other += (my_x == s_dstL[p][j]);
        }
    } else {
        const int i = h - L;
        if (s_srcL[p][i] == did) atomicAdd(&s_cs[p], 1);
        my_x = s_dstL[p][i];
        #pragma unroll
        for (int j = 0; j < L; ++j) {
            c_self  += (my_x == s_dstL[p][j]);
            c_other += (my_x == s_srcL[p][j]);
        }
    }
    __syncthreads();

    // ---- dict-mutation overrides (exact reference semantics) ----
    {
        const int  cd     = s_cd[p];
        const int  cs     = s_cs[p];
        const bool same   = (sid == did);
        const bool in_dst = (cd > 0);                      // srcid_in_dst
        const bool cond2  = (cs > 0) || (same && in_dst);
        const int  v2     = (same && in_dst) ? cd : cs;
        int a0, a1;
        if (h < L) {
            a0 = c_self;                                         // c_src
            a1 = (my_x == did && cond2)  ? v2 : c_other;         // src_col1
        } else {
            a0 = (my_x == sid && in_dst) ? cd : c_other;         // dst_col0
            a1 = c_self;                                         // c_dst
        }
        s_a[p][h] = a0 | (a1 << 8);
    }
    __syncthreads();

    // ---- barrier-free streaming store: 256 rows, one row per warp-iter ----
    // Table rows read straight from g_T via L1 (33 KB, fully L1-resident).
    const float4* gT4 = (const float4*)g_T;   // [TMAX][32] float4

    #pragma unroll 8
    for (int it = 0; it < 32; ++it) {
        const int g  = it * 8 + wrp;          // global row 0..255
        const int pp = g >> 7;                // batch within block
        const int r  = g & 127;               // row within batch
        const int packed = s_a[pp][r];
        const int a0 = packed & 0xFF;
        const int a1 = packed >> 8;
        const float4 t0 = __ldg(&gT4[a0 * 32 + lane]);
        const float4 t1 = __ldg(&gT4[a1 * 32 + lane]);
        float4 o;
        o.x = t0.x + t1.x; o.y = t0.y + t1.y;
        o.z = t0.z + t1.z; o.w = t0.w + t1.w;
        const int bb = base + pp;
        float* dst_row = (r < L)
            ? (out + (size_t)bb * L * D + r * D)
            : (out + half + (size_t)bb * L * D + (r - L) * D);
        __stcs((float4*)&dst_row[lane * 4], o);
    }
}

extern "C" void kernel_launch(void* const* d_in, const int* in_sizes, int n_in,
                              void* d_out, int out_size)
{
    const int*   src_ids = (const int*)  d_in[0];
    const int*   dst_ids = (const int*)  d_in[1];
    const int*   src_nb  = (const int*)  d_in[2];
    const int*   dst_nb  = (const int*)  d_in[3];
    const float* W1      = (const float*)d_in[4];
    const float* b1      = (const float*)d_in[5];
    const float* W2      = (const float*)d_in[6];
    const float* b2      = (const float*)d_in[7];
    float*       out     = (float*)d_out;

    build_table_kernel<<<TMAX, D>>>(W1, b1, W2, b2);
    nif_encoder_kernel<<<GRID, THREADS>>>(src_ids, dst_ids, src_nb, dst_nb, out);
}